// round 5
// baseline (speedup 1.0000x reference)
#include <cuda_runtime.h>
#include <cstdint>
#include <math.h>

#define T_DIM 512
#define B_DIM 256
#define H_DIM 256
#define H3    768
#define M_TOT (T_DIM * B_DIM)
#define NCTA  128

// Precomputed input gates, TRANSPOSED layout: gi_T[t][col][b], col in [0,3H)
__device__ float g_giT[(size_t)T_DIM * H3 * B_DIM];

// Grid barrier state (self-restoring across graph replays: even # of barriers)
__device__ unsigned g_bar_count;
__device__ volatile unsigned g_bar_sense;

// ---------------------------------------------------------------------------
// Kernel 1: GI = ins @ Wi + bi  (M=131072, K=256, N=768), stores transposed.
// Tiles: BM=64, BN=64, BK=16, 256 threads, 4x4 per thread.
// ---------------------------------------------------------------------------
__global__ __launch_bounds__(256) void gi_gemm(const float* __restrict__ A,
                                               const float* __restrict__ Wi,
                                               const float* __restrict__ bi) {
    const int BM = 64, BN = 64, BK = 16;
    __shared__ float As[BK][BM];
    __shared__ float Bs[BK][BN];

    const int m0 = blockIdx.x * BM;
    const int n0 = blockIdx.y * BN;
    const int tid = threadIdx.x;
    const int tx = tid % 16;
    const int ty = tid / 16;

    const int ar = tid >> 2;
    const int ac = tid & 3;
    const int br = tid >> 4;
    const int bc = tid & 15;

    float acc[4][4] = {};

    for (int k0 = 0; k0 < 256; k0 += BK) {
        float4 av = *(const float4*)&A[(size_t)(m0 + ar) * 256 + k0 + ac * 4];
        As[ac * 4 + 0][ar] = av.x;
        As[ac * 4 + 1][ar] = av.y;
        As[ac * 4 + 2][ar] = av.z;
        As[ac * 4 + 3][ar] = av.w;
        *(float4*)&Bs[br][bc * 4] =
            *(const float4*)&Wi[(size_t)(k0 + br) * H3 + n0 + bc * 4];
        __syncthreads();

        #pragma unroll
        for (int k = 0; k < BK; k++) {
            float4 a = *(const float4*)&As[k][ty * 4];
            float4 b = *(const float4*)&Bs[k][tx * 4];
            acc[0][0] += a.x * b.x; acc[0][1] += a.x * b.y; acc[0][2] += a.x * b.z; acc[0][3] += a.x * b.w;
            acc[1][0] += a.y * b.x; acc[1][1] += a.y * b.y; acc[1][2] += a.y * b.z; acc[1][3] += a.y * b.w;
            acc[2][0] += a.z * b.x; acc[2][1] += a.z * b.y; acc[2][2] += a.z * b.z; acc[2][3] += a.z * b.w;
            acc[3][0] += a.w * b.x; acc[3][1] += a.w * b.y; acc[3][2] += a.w * b.z; acc[3][3] += a.w * b.w;
        }
        __syncthreads();
    }

    // Transposed store: gi_T[t][col][b].  Block's 64 rows share one t.
    const int tt  = m0 >> 8;            // t index (m0 multiple of 64, B=256)
    const int bb0 = (m0 & 255) + ty * 4;
    float4 bb = *(const float4*)&bi[n0 + tx * 4];
    const float bias[4] = { bb.x, bb.y, bb.z, bb.w };
    #pragma unroll
    for (int j = 0; j < 4; j++) {
        const int col = n0 + tx * 4 + j;
        float4 o;
        o.x = acc[0][j] + bias[j];
        o.y = acc[1][j] + bias[j];
        o.z = acc[2][j] + bias[j];
        o.w = acc[3][j] + bias[j];
        *(float4*)&g_giT[((size_t)tt * H3 + col) * B_DIM + bb0] = o;
    }
}

// ---------------------------------------------------------------------------
// Grid barrier: sense-reversing, single atomic counter. State returns to
// initial (0,0) after an even number of barriers -> graph-replay safe.
// ---------------------------------------------------------------------------
__device__ __forceinline__ void grid_barrier(unsigned& sense) {
    __syncthreads();
    sense ^= 1u;
    if (threadIdx.x == 0) {
        __threadfence();
        unsigned pos = atomicAdd(&g_bar_count, 1u);
        if (pos == NCTA - 1) {
            atomicExch(&g_bar_count, 0u);
            __threadfence();
            g_bar_sense = sense;
        } else {
            while (g_bar_sense != sense) { }
            __threadfence();
        }
    }
    __syncthreads();
}

// ---------------------------------------------------------------------------
// Kernel 2: persistent scan. 128 CTAs x 256 threads. CTA owns 2 hidden units
// (6 Wh columns cached in smem for the whole scan). Thread owns 1 batch row.
// One grid barrier per step (512 total, even).
// ---------------------------------------------------------------------------
__global__ __launch_bounds__(256) void gru_scan(
    const float* __restrict__ carry,    // [B,H]
    const int*   __restrict__ resets,   // [T,B] int32 bool
    const float* __restrict__ Wh,       // [H,3H]
    const float* __restrict__ bhn,      // [H]
    float*       __restrict__ out)      // [T,B,H]
{
    __shared__ __align__(16) float ws[6][H_DIM];  // ws[c][k], c = gate*2 + unit

    const int tid = threadIdx.x;
    const int j0  = blockIdx.x * 2;     // first hidden unit owned by this CTA

    // Preload Wh slice (once): ws[c][k] = Wh[k, gate*H + j0 + unit]
    #pragma unroll
    for (int c = 0; c < 6; c++) {
        const int g = c >> 1, u = c & 1;
        ws[c][tid] = Wh[(size_t)tid * H3 + g * H_DIM + j0 + u];
    }
    const float bn0 = bhn[j0];
    const float bn1 = bhn[j0 + 1];
    __syncthreads();

    unsigned sense = 0;
    const int b = tid;

    for (int t = 0; t < T_DIM; t++) {
        const float* __restrict__ hprev =
            (t == 0) ? carry : out + (size_t)(t - 1) * B_DIM * H_DIM;

        // Early loads (latency overlapped with the GEMM loop below)
        const int rst = resets[t * B_DIM + b];
        const size_t gb = (size_t)t * H3 * B_DIM + b;
        const float gi_r0 = g_giT[gb + (size_t)(j0            ) * B_DIM];
        const float gi_r1 = g_giT[gb + (size_t)(j0 + 1        ) * B_DIM];
        const float gi_z0 = g_giT[gb + (size_t)(H_DIM + j0    ) * B_DIM];
        const float gi_z1 = g_giT[gb + (size_t)(H_DIM + j0 + 1) * B_DIM];
        const float gi_n0 = g_giT[gb + (size_t)(2*H_DIM + j0    ) * B_DIM];
        const float gi_n1 = g_giT[gb + (size_t)(2*H_DIM + j0 + 1) * B_DIM];
        const float hpj0  = hprev[(size_t)b * H_DIM + j0];
        const float hpj1  = hprev[(size_t)b * H_DIM + j0 + 1];

        // gh accumulation: 6 dot products of length 256
        float a0 = 0.f, a1 = 0.f, a2 = 0.f, a3 = 0.f, a4 = 0.f, a5 = 0.f;
        const float4* hrow = (const float4*)(hprev + (size_t)b * H_DIM);
        #pragma unroll 8
        for (int k4 = 0; k4 < H_DIM / 4; k4++) {
            const float4 hv = hrow[k4];
            const float4 w0 = *(const float4*)&ws[0][k4 * 4];
            const float4 w1 = *(const float4*)&ws[1][k4 * 4];
            const float4 w2 = *(const float4*)&ws[2][k4 * 4];
            const float4 w3 = *(const float4*)&ws[3][k4 * 4];
            const float4 w4 = *(const float4*)&ws[4][k4 * 4];
            const float4 w5 = *(const float4*)&ws[5][k4 * 4];
            a0 += hv.x * w0.x + hv.y * w0.y + hv.z * w0.z + hv.w * w0.w;
            a1 += hv.x * w1.x + hv.y * w1.y + hv.z * w1.z + hv.w * w1.w;
            a2 += hv.x * w2.x + hv.y * w2.y + hv.z * w2.z + hv.w * w2.w;
            a3 += hv.x * w3.x + hv.y * w3.y + hv.z * w3.z + hv.w * w3.w;
            a4 += hv.x * w4.x + hv.y * w4.y + hv.z * w4.z + hv.w * w4.w;
            a5 += hv.x * w5.x + hv.y * w5.y + hv.z * w5.z + hv.w * w5.w;
        }

        // Reset masking (uniform, no divergence)
        const float m = rst ? 0.f : 1.f;
        const float hm0 = m * hpj0;
        const float hm1 = m * hpj1;

        const float r0 = 1.f / (1.f + expf(-(gi_r0 + m * a0)));
        const float r1 = 1.f / (1.f + expf(-(gi_r1 + m * a1)));
        const float z0 = 1.f / (1.f + expf(-(gi_z0 + m * a2)));
        const float z1 = 1.f / (1.f + expf(-(gi_z1 + m * a3)));
        const float n0 = tanhf(gi_n0 + r0 * (m * a4 + bn0));
        const float n1 = tanhf(gi_n1 + r1 * (m * a5 + bn1));

        float* orow = out + (size_t)t * B_DIM * H_DIM + (size_t)b * H_DIM;
        orow[j0]     = (1.f - z0) * n0 + z0 * hm0;
        orow[j0 + 1] = (1.f - z1) * n1 + z1 * hm1;

        grid_barrier(sense);   // out[t] visible chip-wide before step t+1
    }
}

// ---------------------------------------------------------------------------
extern "C" void kernel_launch(void* const* d_in, const int* in_sizes, int n_in,
                              void* d_out, int out_size) {
    const float* ins    = (const float*)d_in[0];   // [T,B,H]
    const int*   resets = (const int*)d_in[1];     // [T,B] int32 (bool promoted)
    const float* carry  = (const float*)d_in[2];   // [B,H]
    const float* Wi     = (const float*)d_in[3];   // [H,3H]
    const float* bi     = (const float*)d_in[4];   // [3H]
    const float* Wh     = (const float*)d_in[5];   // [H,3H]
    const float* bhn    = (const float*)d_in[6];   // [H]
    float*       out    = (float*)d_out;           // [T,B,H]

    // Phase 1: all input gates in parallel (writes g_giT transposed)
    dim3 g1(M_TOT / 64, H3 / 64);
    gi_gemm<<<g1, 256>>>(ins, Wi, bi);

    // Phase 2: the whole 512-step scan in ONE persistent kernel
    gru_scan<<<NCTA, 256>>>(carry, resets, Wh, bhn, out);
}

// round 6
// speedup vs baseline: 2.7568x; 2.7568x over previous
#include <cuda_runtime.h>
#include <cstdint>
#include <math.h>

#define T_DIM 512
#define B_DIM 256
#define H_DIM 256
#define H3    768
#define M_TOT (T_DIM * B_DIM)
#define NCTA  148

// Precomputed input gates gi = ins @ Wi + bi : [T*B][3H] fp32 (402 MB)
__device__ float g_gi[(size_t)M_TOT * H3];
// Wave scheduling
__device__ int g_wave_cnt[T_DIM];      // items per depth
__device__ int g_items[M_TOT];         // item = (t<<8)|b, grouped by depth
// Grid barrier state (re-initialized by prep each replay)
__device__ unsigned g_bar_count;
__device__ volatile unsigned g_bar_sense;

// ---------------------------------------------------------------------------
// Kernel 1: GI = ins @ Wi + bi  (M=131072, K=256, N=768), natural layout.
// ---------------------------------------------------------------------------
__global__ __launch_bounds__(256) void gi_gemm(const float* __restrict__ A,
                                               const float* __restrict__ Wi,
                                               const float* __restrict__ bi) {
    const int BM = 64, BN = 64, BK = 16;
    __shared__ float As[BK][BM];
    __shared__ float Bs[BK][BN];

    const int m0 = blockIdx.x * BM;
    const int n0 = blockIdx.y * BN;
    const int tid = threadIdx.x;
    const int tx = tid % 16;
    const int ty = tid / 16;
    const int ar = tid >> 2;
    const int ac = tid & 3;
    const int br = tid >> 4;
    const int bc = tid & 15;

    float acc[4][4] = {};

    for (int k0 = 0; k0 < 256; k0 += BK) {
        float4 av = *(const float4*)&A[(size_t)(m0 + ar) * 256 + k0 + ac * 4];
        As[ac * 4 + 0][ar] = av.x;
        As[ac * 4 + 1][ar] = av.y;
        As[ac * 4 + 2][ar] = av.z;
        As[ac * 4 + 3][ar] = av.w;
        *(float4*)&Bs[br][bc * 4] =
            *(const float4*)&Wi[(size_t)(k0 + br) * H3 + n0 + bc * 4];
        __syncthreads();

        #pragma unroll
        for (int k = 0; k < BK; k++) {
            float4 a = *(const float4*)&As[k][ty * 4];
            float4 b = *(const float4*)&Bs[k][tx * 4];
            acc[0][0] += a.x * b.x; acc[0][1] += a.x * b.y; acc[0][2] += a.x * b.z; acc[0][3] += a.x * b.w;
            acc[1][0] += a.y * b.x; acc[1][1] += a.y * b.y; acc[1][2] += a.y * b.z; acc[1][3] += a.y * b.w;
            acc[2][0] += a.z * b.x; acc[2][1] += a.z * b.y; acc[2][2] += a.z * b.z; acc[2][3] += a.z * b.w;
            acc[3][0] += a.w * b.x; acc[3][1] += a.w * b.y; acc[3][2] += a.w * b.z; acc[3][3] += a.w * b.w;
        }
        __syncthreads();
    }

    float4 bb = *(const float4*)&bi[n0 + tx * 4];
    #pragma unroll
    for (int i = 0; i < 4; i++) {
        const size_t row = (size_t)(m0 + ty * 4 + i);
        float4 o;
        o.x = acc[i][0] + bb.x;
        o.y = acc[i][1] + bb.y;
        o.z = acc[i][2] + bb.z;
        o.w = acc[i][3] + bb.w;
        *(float4*)&g_gi[row * H3 + n0 + tx * 4] = o;
    }
}

// ---------------------------------------------------------------------------
// Kernel 2: prep. 1 CTA x 256 threads (thread = batch column b).
// Computes depth d(t,b), per-depth counts, and fills g_items grouped by depth.
// Also resets the grid-barrier state for this replay.
// ---------------------------------------------------------------------------
__global__ __launch_bounds__(256) void prep(const int* __restrict__ resets) {
    __shared__ int s_cnt[T_DIM];
    __shared__ int s_cur[T_DIM];
    const int tid = threadIdx.x;
    for (int i = tid; i < T_DIM; i += 256) s_cnt[i] = 0;
    if (tid == 0) { g_bar_count = 0; g_bar_sense = 0; }
    __syncthreads();

    const int b = tid;
    // Pass 1: counts (warp-aggregated)
    int d = 0;
    for (int t = 0; t < T_DIM; t++) {
        const int rst = resets[t * B_DIM + b];
        d = (t == 0 || rst) ? 0 : d + 1;
        const unsigned mask = __match_any_sync(0xffffffffu, d);
        const int leader = __ffs(mask) - 1;
        if ((tid & 31) == leader) atomicAdd(&s_cnt[d], __popc(mask));
    }
    __syncthreads();
    // Prefix sum (serial, 512 iters)
    if (tid == 0) {
        int acc = 0;
        for (int i = 0; i < T_DIM; i++) {
            const int c = s_cnt[i];
            g_wave_cnt[i] = c;
            s_cur[i] = acc;
            acc += c;
        }
    }
    __syncthreads();
    // Pass 2: fill item lists
    d = 0;
    for (int t = 0; t < T_DIM; t++) {
        const int rst = resets[t * B_DIM + b];
        d = (t == 0 || rst) ? 0 : d + 1;
        const unsigned mask = __match_any_sync(0xffffffffu, d);
        const int leader = __ffs(mask) - 1;
        int base = 0;
        if ((tid & 31) == leader) base = atomicAdd(&s_cur[d], __popc(mask));
        base = __shfl_sync(0xffffffffu, base, leader);
        const int rank = __popc(mask & ((1u << (tid & 31)) - 1u));
        g_items[base + rank] = (t << 8) | b;
    }
}

// ---------------------------------------------------------------------------
// Grid barrier (sense-reversing; state reset by prep each replay)
// ---------------------------------------------------------------------------
__device__ __forceinline__ void grid_barrier(unsigned& sense) {
    __syncthreads();
    sense ^= 1u;
    if (threadIdx.x == 0) {
        __threadfence();
        const unsigned pos = atomicAdd(&g_bar_count, 1u);
        if (pos == NCTA - 1) {
            atomicExch(&g_bar_count, 0u);
            __threadfence();
            g_bar_sense = sense;
        } else {
            while (g_bar_sense != sense) { __nanosleep(40); }
            __threadfence();
        }
    }
    __syncthreads();
}

// ---------------------------------------------------------------------------
// Kernel 3: wave GEMM scan. Persistent 148 CTAs x 256 threads.
// Wave i: gathered GEMM [n_i, 256] @ Wh[256, 768] + fused gates, writing y.
// Tile: 64 items x 64 j-cols x 3 gates. Grid barrier between waves only.
// ---------------------------------------------------------------------------
__global__ __launch_bounds__(256) void gru_waves(
    const float* __restrict__ carry,    // [B,H]
    const int*   __restrict__ resets,   // [T,B]
    const float* __restrict__ Wh,       // [H,3H]
    const float* __restrict__ bhn,      // [H]
    float*       __restrict__ out)      // [T,B,H]
{
    __shared__ float As[16][64];
    __shared__ float Bs[3][16][64];
    __shared__ const float* s_ptr[64];  // masked h source row (null = zeros)
    __shared__ int s_item[64];

    const int tid = threadIdx.x;
    const int tx = tid & 15;
    const int ty = tid >> 4;
    const int ar = tid >> 2;
    const int ac = tid & 3;

    unsigned sense = 0;
    int off = 0;

    for (int w = 0; w < T_DIM; w++) {
        const int n = g_wave_cnt[w];
        if (n == 0) break;
        const int ntiles = ((n + 63) >> 6) << 2;   // m-tiles * 4 j-tiles

        for (int tile = blockIdx.x; tile < ntiles; tile += NCTA) {
            const int m0 = (tile >> 2) << 6;
            const int j0 = (tile & 3) << 6;

            __syncthreads();   // protect s_ptr/s_item reuse across tiles
            if (tid < 64) {
                const int m = m0 + tid;
                const float* p = nullptr;
                int item = 0;
                if (m < n) {
                    item = g_items[off + m];
                    const int t = item >> 8;
                    const int b = item & 255;
                    if (!resets[t * B_DIM + b])
                        p = (t == 0) ? (carry + (size_t)b * H_DIM)
                                     : (out + ((size_t)(t - 1) * B_DIM + b) * H_DIM);
                }
                s_ptr[tid]  = p;
                s_item[tid] = item;
            }
            __syncthreads();

            float acc[3][4][4];
            #pragma unroll
            for (int g = 0; g < 3; g++)
                #pragma unroll
                for (int i = 0; i < 4; i++)
                    #pragma unroll
                    for (int c = 0; c < 4; c++) acc[g][i][c] = 0.f;

            for (int k0 = 0; k0 < H_DIM; k0 += 16) {
                const float* p = s_ptr[ar];
                float4 av = p ? *(const float4*)(p + k0 + ac * 4)
                              : make_float4(0.f, 0.f, 0.f, 0.f);
                As[ac * 4 + 0][ar] = av.x;
                As[ac * 4 + 1][ar] = av.y;
                As[ac * 4 + 2][ar] = av.z;
                As[ac * 4 + 3][ar] = av.w;
                #pragma unroll
                for (int g = 0; g < 3; g++)
                    *(float4*)&Bs[g][ty][tx * 4] =
                        *(const float4*)&Wh[(size_t)(k0 + ty) * H3 + g * H_DIM + j0 + tx * 4];
                __syncthreads();

                #pragma unroll
                for (int k = 0; k < 16; k++) {
                    const float4 a  = *(const float4*)&As[k][ty * 4];
                    const float4 br = *(const float4*)&Bs[0][k][tx * 4];
                    const float4 bz = *(const float4*)&Bs[1][k][tx * 4];
                    const float4 bn = *(const float4*)&Bs[2][k][tx * 4];
                    const float avv[4] = { a.x, a.y, a.z, a.w };
                    const float brv[4] = { br.x, br.y, br.z, br.w };
                    const float bzv[4] = { bz.x, bz.y, bz.z, bz.w };
                    const float bnv[4] = { bn.x, bn.y, bn.z, bn.w };
                    #pragma unroll
                    for (int i = 0; i < 4; i++)
                        #pragma unroll
                        for (int c = 0; c < 4; c++) {
                            acc[0][i][c] += avv[i] * brv[c];
                            acc[1][i][c] += avv[i] * bzv[c];
                            acc[2][i][c] += avv[i] * bnv[c];
                        }
                }
                __syncthreads();
            }

            // Fused gate epilogue
            const int j = j0 + tx * 4;
            const float4 bn4 = *(const float4*)&bhn[j];
            const float bnv[4] = { bn4.x, bn4.y, bn4.z, bn4.w };
            #pragma unroll
            for (int i = 0; i < 4; i++) {
                const int m = m0 + ty * 4 + i;
                if (m >= n) continue;
                const int item = s_item[ty * 4 + i];       // = t*256+b = row idx
                const float* p = s_ptr[ty * 4 + i];
                const float* gi = g_gi + (size_t)item * H3 + j;
                const float4 gr = *(const float4*)gi;
                const float4 gz = *(const float4*)(gi + H_DIM);
                const float4 gn = *(const float4*)(gi + 2 * H_DIM);
                const float4 hp = p ? *(const float4*)(p + j)
                                    : make_float4(0.f, 0.f, 0.f, 0.f);
                const float grv[4] = { gr.x, gr.y, gr.z, gr.w };
                const float gzv[4] = { gz.x, gz.y, gz.z, gz.w };
                const float gnv[4] = { gn.x, gn.y, gn.z, gn.w };
                const float hpv[4] = { hp.x, hp.y, hp.z, hp.w };
                float o[4];
                #pragma unroll
                for (int c = 0; c < 4; c++) {
                    const float r  = 1.f / (1.f + expf(-(grv[c] + acc[0][i][c])));
                    const float z  = 1.f / (1.f + expf(-(gzv[c] + acc[1][i][c])));
                    const float nn = tanhf(gnv[c] + r * (acc[2][i][c] + bnv[c]));
                    o[c] = (1.f - z) * nn + z * hpv[c];
                }
                *(float4*)(out + (size_t)item * H_DIM + j) =
                    make_float4(o[0], o[1], o[2], o[3]);
            }
        }

        off += n;
        grid_barrier(sense);   // wave w outputs visible before wave w+1
    }
}

// ---------------------------------------------------------------------------
extern "C" void kernel_launch(void* const* d_in, const int* in_sizes, int n_in,
                              void* d_out, int out_size) {
    const float* ins    = (const float*)d_in[0];   // [T,B,H]
    const int*   resets = (const int*)d_in[1];     // [T,B] int32 (bool promoted)
    const float* carry  = (const float*)d_in[2];   // [B,H]
    const float* Wi     = (const float*)d_in[3];   // [H,3H]
    const float* bi     = (const float*)d_in[4];   // [3H]
    const float* Wh     = (const float*)d_in[5];   // [H,3H]
    const float* bhn    = (const float*)d_in[6];   // [H]
    float*       out    = (float*)d_out;           // [T,B,H]

    // Phase 1: all input gates in parallel
    dim3 g1(M_TOT / 64, H3 / 64);
    gi_gemm<<<g1, 256>>>(ins, Wi, bi);

    // Phase 2: wave schedule from resets (+ barrier state reset)
    prep<<<1, 256>>>(resets);

    // Phase 3: ~20 dependency waves, one persistent kernel
    gru_waves<<<NCTA, 256>>>(carry, resets, Wh, bhn, out);
}

// round 7
// speedup vs baseline: 4.7686x; 1.7298x over previous
#include <cuda_runtime.h>
#include <cuda_bf16.h>
#include <cstdint>
#include <math.h>

#define T_DIM 512
#define B_DIM 256
#define H_DIM 256
#define H3    768
#define M_TOT (T_DIM * B_DIM)
#define NCTA  148

// Precomputed input gates gi = ins @ Wi + bi : [T*B][3H] fp32 (402 MB)
__device__ float g_gi[(size_t)M_TOT * H3];
// Pre-split weights (bf16 hi/lo), row-major [K][3H]
__device__ __nv_bfloat16 g_wi_h[H_DIM * H3], g_wi_l[H_DIM * H3];
__device__ __nv_bfloat16 g_wh_h[H_DIM * H3], g_wh_l[H_DIM * H3];
// Wave scheduling
__device__ int g_wave_cnt[T_DIM];
__device__ int g_items[M_TOT];         // item = (t<<8)|b = row index
// Grid barrier state (re-initialized by prep each replay)
__device__ unsigned g_bar_count;
__device__ volatile unsigned g_bar_sense;

// ---------------------------------------------------------------------------
// PTX helpers: ldmatrix + bf16 mma (fragment layouts per PTX ISA m16n8k16)
// ---------------------------------------------------------------------------
__device__ __forceinline__ uint32_t smem_u32(const void* p) {
    return (uint32_t)__cvta_generic_to_shared(p);
}
__device__ __forceinline__ void ldsm_x4(uint32_t* r, uint32_t a) {
    asm volatile("ldmatrix.sync.aligned.m8n8.x4.shared.b16 {%0,%1,%2,%3}, [%4];"
                 : "=r"(r[0]), "=r"(r[1]), "=r"(r[2]), "=r"(r[3]) : "r"(a));
}
__device__ __forceinline__ void ldsm_x2t(uint32_t* r, uint32_t a) {
    asm volatile("ldmatrix.sync.aligned.m8n8.x2.trans.shared.b16 {%0,%1}, [%2];"
                 : "=r"(r[0]), "=r"(r[1]) : "r"(a));
}
__device__ __forceinline__ void mma_bf16(float* c, const uint32_t* a, const uint32_t* b) {
    asm volatile("mma.sync.aligned.m16n8k16.row.col.f32.bf16.bf16.f32 "
                 "{%0,%1,%2,%3}, {%4,%5,%6,%7}, {%8,%9}, {%0,%1,%2,%3};"
                 : "+f"(c[0]), "+f"(c[1]), "+f"(c[2]), "+f"(c[3])
                 : "r"(a[0]), "r"(a[1]), "r"(a[2]), "r"(a[3]),
                   "r"(b[0]), "r"(b[1]));
}
// split fp32 -> (hi, lo) bf16 pair
__device__ __forceinline__ void split4(__nv_bfloat16* dh, __nv_bfloat16* dl, float4 v) {
    float vv[4] = { v.x, v.y, v.z, v.w };
    __nv_bfloat16 h[4], l[4];
    #pragma unroll
    for (int i = 0; i < 4; i++) {
        h[i] = __float2bfloat16(vv[i]);
        l[i] = __float2bfloat16(vv[i] - __bfloat162float(h[i]));
    }
    *(__nv_bfloat162*)&dh[0] = __nv_bfloat162(h[0], h[1]);
    *(__nv_bfloat162*)&dh[2] = __nv_bfloat162(h[2], h[3]);
    *(__nv_bfloat162*)&dl[0] = __nv_bfloat162(l[0], l[1]);
    *(__nv_bfloat162*)&dl[2] = __nv_bfloat162(l[2], l[3]);
}

// ---------------------------------------------------------------------------
// Kernel 0: split Wi and Wh into bf16 hi/lo (once per replay; tiny)
// ---------------------------------------------------------------------------
__global__ __launch_bounds__(256) void w_prep(const float* __restrict__ Wi,
                                              const float* __restrict__ Wh) {
    const int i = blockIdx.x * 256 + threadIdx.x;
    if (i < H_DIM * H3) {
        float v = Wi[i];
        __nv_bfloat16 h = __float2bfloat16(v);
        g_wi_h[i] = h;
        g_wi_l[i] = __float2bfloat16(v - __bfloat162float(h));
        v = Wh[i];
        h = __float2bfloat16(v);
        g_wh_h[i] = h;
        g_wh_l[i] = __float2bfloat16(v - __bfloat162float(h));
    }
}

// ---------------------------------------------------------------------------
// Kernel 1: GI = ins @ Wi + bi   (M=131072, K=256, N=768)  — tensor cores.
// BM=128, BN=128, BK=32. 8 warps: 4(M) x 2(N); warp tile m32 x n64.
// Grid: x = n-tile (6, fastest -> A-tile L2 reuse), y = m-tile (1024).
// ---------------------------------------------------------------------------
#define LDA 40
#define LDBg 136
__global__ __launch_bounds__(256) void gi_gemm(const float* __restrict__ A,
                                               const float* __restrict__ bi) {
    __shared__ __align__(16) __nv_bfloat16 Ah[128][LDA], Al[128][LDA];
    __shared__ __align__(16) __nv_bfloat16 Bh[32][LDBg], Bl[32][LDBg];

    const int tid = threadIdx.x;
    const int wid = tid >> 5, lane = tid & 31;
    const int m0 = blockIdx.y * 128, n0 = blockIdx.x * 128;
    const int wm = (wid >> 1) * 32, wn = (wid & 1) * 64;
    const int g = lane >> 2, tg = lane & 3;

    const int arow = tid >> 1, acb = (tid & 1) * 16;   // A: 128 rows x 32 cols
    const int brow = tid >> 3, bcb = (tid & 7) * 16;   // B: 32 rows x 128 cols

    float acc[2][8][4];
    #pragma unroll
    for (int mb = 0; mb < 2; mb++)
        #pragma unroll
        for (int nb = 0; nb < 8; nb++)
            #pragma unroll
            for (int q = 0; q < 4; q++) acc[mb][nb][q] = 0.f;

    for (int k0 = 0; k0 < H_DIM; k0 += 32) {
        // A tile: fp32 -> split bf16
        #pragma unroll
        for (int q = 0; q < 4; q++) {
            float4 v = *(const float4*)&A[(size_t)(m0 + arow) * H_DIM + k0 + acb + q * 4];
            split4(&Ah[arow][acb + q * 4], &Al[arow][acb + q * 4], v);
        }
        // B tile: straight bf16 copy from pre-split weights
        {
            const size_t src = (size_t)(k0 + brow) * H3 + n0 + bcb;
            *(uint4*)&Bh[brow][bcb]     = *(const uint4*)&g_wi_h[src];
            *(uint4*)&Bh[brow][bcb + 8] = *(const uint4*)&g_wi_h[src + 8];
            *(uint4*)&Bl[brow][bcb]     = *(const uint4*)&g_wi_l[src];
            *(uint4*)&Bl[brow][bcb + 8] = *(const uint4*)&g_wi_l[src + 8];
        }
        __syncthreads();

        #pragma unroll
        for (int ks = 0; ks < 2; ks++) {
            const int kk = ks * 16;
            uint32_t afh[2][4], afl[2][4];
            #pragma unroll
            for (int mb = 0; mb < 2; mb++) {
                const int r = wm + mb * 16 + (lane & 15);
                const int c = kk + (lane >> 4) * 8;
                ldsm_x4(afh[mb], smem_u32(&Ah[r][c]));
                ldsm_x4(afl[mb], smem_u32(&Al[r][c]));
            }
            #pragma unroll
            for (int nb = 0; nb < 8; nb++) {
                uint32_t bfh[2], bfl[2];
                const int br2 = kk + (lane & 15);
                const int bc2 = wn + nb * 8;
                ldsm_x2t(bfh, smem_u32(&Bh[br2][bc2]));
                ldsm_x2t(bfl, smem_u32(&Bl[br2][bc2]));
                #pragma unroll
                for (int mb = 0; mb < 2; mb++) {
                    mma_bf16(acc[mb][nb], afh[mb], bfh);
                    mma_bf16(acc[mb][nb], afh[mb], bfl);
                    mma_bf16(acc[mb][nb], afl[mb], bfh);
                }
            }
        }
        __syncthreads();
    }

    // Epilogue: + bias, write g_gi
    #pragma unroll
    for (int nb = 0; nb < 8; nb++) {
        const int col = n0 + wn + nb * 8 + 2 * tg;
        const float2 bb = *(const float2*)&bi[col];
        #pragma unroll
        for (int mb = 0; mb < 2; mb++) {
            const int row = m0 + wm + mb * 16 + g;
            float2 o0 = { acc[mb][nb][0] + bb.x, acc[mb][nb][1] + bb.y };
            float2 o1 = { acc[mb][nb][2] + bb.x, acc[mb][nb][3] + bb.y };
            *(float2*)&g_gi[(size_t)row * H3 + col]       = o0;
            *(float2*)&g_gi[(size_t)(row + 8) * H3 + col] = o1;
        }
    }
}

// ---------------------------------------------------------------------------
// Kernel 2: prep. 1 CTA x 256 threads: wave schedule + barrier reset.
// ---------------------------------------------------------------------------
__global__ __launch_bounds__(256) void prep(const int* __restrict__ resets) {
    __shared__ int s_cnt[T_DIM];
    __shared__ int s_cur[T_DIM];
    const int tid = threadIdx.x;
    for (int i = tid; i < T_DIM; i += 256) s_cnt[i] = 0;
    if (tid == 0) { g_bar_count = 0; g_bar_sense = 0; }
    __syncthreads();

    const int b = tid;
    int d = 0;
    for (int t = 0; t < T_DIM; t++) {
        const int rst = resets[t * B_DIM + b];
        d = (t == 0 || rst) ? 0 : d + 1;
        const unsigned mask = __match_any_sync(0xffffffffu, d);
        const int leader = __ffs(mask) - 1;
        if ((tid & 31) == leader) atomicAdd(&s_cnt[d], __popc(mask));
    }
    __syncthreads();
    if (tid == 0) {
        int acc = 0;
        for (int i = 0; i < T_DIM; i++) {
            const int c = s_cnt[i];
            g_wave_cnt[i] = c;
            s_cur[i] = acc;
            acc += c;
        }
    }
    __syncthreads();
    d = 0;
    for (int t = 0; t < T_DIM; t++) {
        const int rst = resets[t * B_DIM + b];
        d = (t == 0 || rst) ? 0 : d + 1;
        const unsigned mask = __match_any_sync(0xffffffffu, d);
        const int leader = __ffs(mask) - 1;
        int base = 0;
        if ((tid & 31) == leader) base = atomicAdd(&s_cur[d], __popc(mask));
        base = __shfl_sync(0xffffffffu, base, leader);
        const int rank = __popc(mask & ((1u << (tid & 31)) - 1u));
        g_items[base + rank] = (t << 8) | b;
    }
}

// ---------------------------------------------------------------------------
// Grid barrier
// ---------------------------------------------------------------------------
__device__ __forceinline__ void grid_barrier(unsigned& sense) {
    __syncthreads();
    sense ^= 1u;
    if (threadIdx.x == 0) {
        __threadfence();
        const unsigned pos = atomicAdd(&g_bar_count, 1u);
        if (pos == NCTA - 1) {
            atomicExch(&g_bar_count, 0u);
            __threadfence();
            g_bar_sense = sense;
        } else {
            while (g_bar_sense != sense) { __nanosleep(40); }
            __threadfence();
        }
    }
    __syncthreads();
}

// ---------------------------------------------------------------------------
// Kernel 3: wave GEMM scan — tensor cores.
// Tile: 64 items x 64 j-cols x 3 gates (BN=192). BK=32. 8 warps: 2(M) x 4(J);
// warp tile m32 x j16 x 3 gates. Grid barrier between waves.
// ---------------------------------------------------------------------------
#define LDBw 200
__global__ __launch_bounds__(256) void gru_waves(
    const float* __restrict__ carry,    // [B,H]
    const int*   __restrict__ resets,   // [T,B]
    const float* __restrict__ bhn,      // [H]
    float*       __restrict__ out)      // [T,B,H]
{
    __shared__ __align__(16) __nv_bfloat16 Ah[64][LDA], Al[64][LDA];
    __shared__ __align__(16) __nv_bfloat16 Bh[32][LDBw], Bl[32][LDBw];
    __shared__ const float* s_ptr[64];
    __shared__ int s_item[64];

    const int tid = threadIdx.x;
    const int wid = tid >> 5, lane = tid & 31;
    const int wm = (wid >> 2) * 32, wj = (wid & 3) * 16;
    const int g = lane >> 2, tg = lane & 3;

    const int garow = tid >> 2, gacb = (tid & 3) * 8;   // A: 64 x 32
    const int gbrow = tid >> 3, gbcb = (tid & 7) * 8;   // B per gate: 32 x 64

    unsigned sense = 0;
    int off = 0;

    for (int w = 0; w < T_DIM; w++) {
        const int n = g_wave_cnt[w];
        if (n == 0) break;
        const int ntiles = ((n + 63) >> 6) << 2;

        for (int tile = blockIdx.x; tile < ntiles; tile += NCTA) {
            const int m0 = (tile >> 2) << 6;
            const int j0 = (tile & 3) << 6;

            __syncthreads();
            if (tid < 64) {
                const int m = m0 + tid;
                const float* p = nullptr;
                int item = 0;
                if (m < n) {
                    item = g_items[off + m];
                    const int t = item >> 8;
                    const int b = item & 255;
                    if (!resets[t * B_DIM + b])
                        p = (t == 0) ? (carry + (size_t)b * H_DIM)
                                     : (out + ((size_t)(t - 1) * B_DIM + b) * H_DIM);
                }
                s_ptr[tid]  = p;
                s_item[tid] = item;
            }
            __syncthreads();

            float acc[2][2][3][4];
            #pragma unroll
            for (int mb = 0; mb < 2; mb++)
                #pragma unroll
                for (int jb = 0; jb < 2; jb++)
                    #pragma unroll
                    for (int gg = 0; gg < 3; gg++)
                        #pragma unroll
                        for (int q = 0; q < 4; q++) acc[mb][jb][gg][q] = 0.f;

            for (int k0 = 0; k0 < H_DIM; k0 += 32) {
                // gathered A rows -> split bf16
                const float* p = s_ptr[garow];
                #pragma unroll
                for (int q = 0; q < 2; q++) {
                    float4 v = p ? *(const float4*)(p + k0 + gacb + q * 4)
                                 : make_float4(0.f, 0.f, 0.f, 0.f);
                    split4(&Ah[garow][gacb + q * 4], &Al[garow][gacb + q * 4], v);
                }
                // Wh tiles per gate: bf16 copy
                #pragma unroll
                for (int gg = 0; gg < 3; gg++) {
                    const size_t src = (size_t)(k0 + gbrow) * H3 + gg * H_DIM + j0 + gbcb;
                    *(uint4*)&Bh[gbrow][gg * 64 + gbcb] = *(const uint4*)&g_wh_h[src];
                    *(uint4*)&Bl[gbrow][gg * 64 + gbcb] = *(const uint4*)&g_wh_l[src];
                }
                __syncthreads();

                #pragma unroll
                for (int ks = 0; ks < 2; ks++) {
                    const int kk = ks * 16;
                    uint32_t afh[2][4], afl[2][4];
                    #pragma unroll
                    for (int mb = 0; mb < 2; mb++) {
                        const int r = wm + mb * 16 + (lane & 15);
                        const int c = kk + (lane >> 4) * 8;
                        ldsm_x4(afh[mb], smem_u32(&Ah[r][c]));
                        ldsm_x4(afl[mb], smem_u32(&Al[r][c]));
                    }
                    #pragma unroll
                    for (int gg = 0; gg < 3; gg++) {
                        #pragma unroll
                        for (int jb = 0; jb < 2; jb++) {
                            uint32_t bfh[2], bfl[2];
                            const int br2 = kk + (lane & 15);
                            const int bc2 = gg * 64 + wj + jb * 8;
                            ldsm_x2t(bfh, smem_u32(&Bh[br2][bc2]));
                            ldsm_x2t(bfl, smem_u32(&Bl[br2][bc2]));
                            #pragma unroll
                            for (int mb = 0; mb < 2; mb++) {
                                mma_bf16(acc[mb][jb][gg], afh[mb], bfh);
                                mma_bf16(acc[mb][jb][gg], afh[mb], bfl);
                                mma_bf16(acc[mb][jb][gg], afl[mb], bfh);
                            }
                        }
                    }
                }
                __syncthreads();
            }

            // Fused GRU epilogue
            #pragma unroll
            for (int jb = 0; jb < 2; jb++) {
                const int j = j0 + wj + jb * 8 + 2 * tg;
                const float2 bn2 = *(const float2*)&bhn[j];
                #pragma unroll
                for (int mb = 0; mb < 2; mb++) {
                    #pragma unroll
                    for (int half = 0; half < 2; half++) {
                        const int lm = wm + mb * 16 + g + half * 8;
                        if (m0 + lm >= n) continue;
                        const int item = s_item[lm];
                        const float* hp_ptr = s_ptr[lm];
                        const float* gip = g_gi + (size_t)item * H3 + j;
                        const float2 gr = *(const float2*)gip;
                        const float2 gz = *(const float2*)(gip + H_DIM);
                        const float2 gn = *(const float2*)(gip + 2 * H_DIM);
                        float2 hp = hp_ptr ? *(const float2*)(hp_ptr + j)
                                           : make_float2(0.f, 0.f);
                        const float aR0 = acc[mb][jb][0][half * 2 + 0];
                        const float aR1 = acc[mb][jb][0][half * 2 + 1];
                        const float aZ0 = acc[mb][jb][1][half * 2 + 0];
                        const float aZ1 = acc[mb][jb][1][half * 2 + 1];
                        const float aN0 = acc[mb][jb][2][half * 2 + 0];
                        const float aN1 = acc[mb][jb][2][half * 2 + 1];
                        const float r0 = 1.f / (1.f + expf(-(gr.x + aR0)));
                        const float r1 = 1.f / (1.f + expf(-(gr.y + aR1)));
                        const float z0 = 1.f / (1.f + expf(-(gz.x + aZ0)));
                        const float z1 = 1.f / (1.f + expf(-(gz.y + aZ1)));
                        const float n0 = tanhf(gn.x + r0 * (aN0 + bn2.x));
                        const float n1 = tanhf(gn.y + r1 * (aN1 + bn2.y));
                        float2 o;
                        o.x = (1.f - z0) * n0 + z0 * hp.x;
                        o.y = (1.f - z1) * n1 + z1 * hp.y;
                        *(float2*)(out + (size_t)item * H_DIM + j) = o;
                    }
                }
            }
        }

        off += n;
        grid_barrier(sense);
    }
}

// ---------------------------------------------------------------------------
extern "C" void kernel_launch(void* const* d_in, const int* in_sizes, int n_in,
                              void* d_out, int out_size) {
    const float* ins    = (const float*)d_in[0];   // [T,B,H]
    const int*   resets = (const int*)d_in[1];     // [T,B] int32 (bool promoted)
    const float* carry  = (const float*)d_in[2];   // [B,H]
    const float* Wi     = (const float*)d_in[3];   // [H,3H]
    const float* bi     = (const float*)d_in[4];   // [3H]
    const float* Wh     = (const float*)d_in[5];   // [H,3H]
    const float* bhn    = (const float*)d_in[6];   // [H]
    float*       out    = (float*)d_out;           // [T,B,H]

    // Phase 0: split weights to bf16 hi/lo
    w_prep<<<(H_DIM * H3 + 255) / 256, 256>>>(Wi, Wh);

    // Phase 1: all input gates via tensor cores (n-tile fastest for A reuse)
    dim3 g1(H3 / 128, M_TOT / 128);
    gi_gemm<<<g1, 256>>>(ins, bi);

    // Phase 2: wave schedule from resets (+ barrier state reset)
    prep<<<1, 256>>>(resets);

    // Phase 3: dependency waves, one persistent kernel, tensor-core GEMMs
    gru_waves<<<NCTA, 256>>>(carry, resets, bhn, out);
}

// round 8
// speedup vs baseline: 6.6596x; 1.3965x over previous
#include <cuda_runtime.h>
#include <cuda_bf16.h>
#include <cstdint>
#include <math.h>

#define T_DIM 512
#define B_DIM 256
#define H_DIM 256
#define H3    768
#define M_TOT (T_DIM * B_DIM)
#define NCTA2 296   // persistent wave kernel: 2 CTAs per SM

// Precomputed input gates gi = ins @ Wi + bi : [T*B][3H] fp32 (402 MB)
__device__ float g_gi[(size_t)M_TOT * H3];
// Pre-split weights (bf16 hi/lo), row-major [K][3H]
__device__ __nv_bfloat16 g_wi_h[H_DIM * H3], g_wi_l[H_DIM * H3];
__device__ __nv_bfloat16 g_wh_h[H_DIM * H3], g_wh_l[H_DIM * H3];
// Wave scheduling
__device__ int g_wave_cnt[T_DIM];
__device__ int g_items[M_TOT];         // item = (t<<8)|b = row index
// Grid barrier state (re-initialized by prep each replay)
__device__ unsigned g_bar_count;
__device__ volatile unsigned g_bar_sense;

// ---------------------------------------------------------------------------
// PTX helpers
// ---------------------------------------------------------------------------
__device__ __forceinline__ uint32_t smem_u32(const void* p) {
    return (uint32_t)__cvta_generic_to_shared(p);
}
__device__ __forceinline__ void ldsm_x4(uint32_t* r, uint32_t a) {
    asm volatile("ldmatrix.sync.aligned.m8n8.x4.shared.b16 {%0,%1,%2,%3}, [%4];"
                 : "=r"(r[0]), "=r"(r[1]), "=r"(r[2]), "=r"(r[3]) : "r"(a));
}
__device__ __forceinline__ void ldsm_x2t(uint32_t* r, uint32_t a) {
    asm volatile("ldmatrix.sync.aligned.m8n8.x2.trans.shared.b16 {%0,%1}, [%2];"
                 : "=r"(r[0]), "=r"(r[1]) : "r"(a));
}
__device__ __forceinline__ void mma_bf16(float* c, const uint32_t* a, const uint32_t* b) {
    asm volatile("mma.sync.aligned.m16n8k16.row.col.f32.bf16.bf16.f32 "
                 "{%0,%1,%2,%3}, {%4,%5,%6,%7}, {%8,%9}, {%0,%1,%2,%3};"
                 : "+f"(c[0]), "+f"(c[1]), "+f"(c[2]), "+f"(c[3])
                 : "r"(a[0]), "r"(a[1]), "r"(a[2]), "r"(a[3]),
                   "r"(b[0]), "r"(b[1]));
}
__device__ __forceinline__ void split4(__nv_bfloat16* dh, __nv_bfloat16* dl, float4 v) {
    float vv[4] = { v.x, v.y, v.z, v.w };
    __nv_bfloat16 h[4], l[4];
    #pragma unroll
    for (int i = 0; i < 4; i++) {
        h[i] = __float2bfloat16(vv[i]);
        l[i] = __float2bfloat16(vv[i] - __bfloat162float(h[i]));
    }
    *(__nv_bfloat162*)&dh[0] = __nv_bfloat162(h[0], h[1]);
    *(__nv_bfloat162*)&dh[2] = __nv_bfloat162(h[2], h[3]);
    *(__nv_bfloat162*)&dl[0] = __nv_bfloat162(l[0], l[1]);
    *(__nv_bfloat162*)&dl[2] = __nv_bfloat162(l[2], l[3]);
}

// ---------------------------------------------------------------------------
// Kernel 0: split Wi and Wh into bf16 hi/lo
// ---------------------------------------------------------------------------
__global__ __launch_bounds__(256) void w_prep(const float* __restrict__ Wi,
                                              const float* __restrict__ Wh) {
    const int i = blockIdx.x * 256 + threadIdx.x;
    if (i < H_DIM * H3) {
        float v = Wi[i];
        __nv_bfloat16 h = __float2bfloat16(v);
        g_wi_h[i] = h;
        g_wi_l[i] = __float2bfloat16(v - __bfloat162float(h));
        v = Wh[i];
        h = __float2bfloat16(v);
        g_wh_h[i] = h;
        g_wh_l[i] = __float2bfloat16(v - __bfloat162float(h));
    }
}

// ---------------------------------------------------------------------------
// Kernel 1: GI = ins @ Wi + bi (tensor cores, register-prefetch pipelined)
// BM=128, BN=128, BK=32. 8 warps: 4(M) x 2(N); warp tile m32 x n64.
// ---------------------------------------------------------------------------
#define LDA 40
#define LDBg 136
__global__ __launch_bounds__(256, 2) void gi_gemm(const float* __restrict__ A,
                                                  const float* __restrict__ bi) {
    __shared__ __align__(16) __nv_bfloat16 Ah[128][LDA], Al[128][LDA];
    __shared__ __align__(16) __nv_bfloat16 Bh[32][LDBg], Bl[32][LDBg];

    const int tid = threadIdx.x;
    const int wid = tid >> 5, lane = tid & 31;
    const int m0 = blockIdx.y * 128, n0 = blockIdx.x * 128;
    const int wm = (wid >> 1) * 32, wn = (wid & 1) * 64;
    const int g = lane >> 2, tg = lane & 3;

    const int arow = tid >> 1, acb = (tid & 1) * 16;
    const int brow = tid >> 3, bcb = (tid & 7) * 16;

    float acc[2][8][4];
    #pragma unroll
    for (int mb = 0; mb < 2; mb++)
        #pragma unroll
        for (int nb = 0; nb < 8; nb++)
            #pragma unroll
            for (int q = 0; q < 4; q++) acc[mb][nb][q] = 0.f;

    // prefetch registers
    float4 pa[4];
    uint4 pbh0, pbh1, pbl0, pbl1;
    {
        #pragma unroll
        for (int q = 0; q < 4; q++)
            pa[q] = *(const float4*)&A[(size_t)(m0 + arow) * H_DIM + acb + q * 4];
        const size_t src = (size_t)brow * H3 + n0 + bcb;
        pbh0 = *(const uint4*)&g_wi_h[src];
        pbh1 = *(const uint4*)&g_wi_h[src + 8];
        pbl0 = *(const uint4*)&g_wi_l[src];
        pbl1 = *(const uint4*)&g_wi_l[src + 8];
    }

    for (int k0 = 0; k0 < H_DIM; k0 += 32) {
        #pragma unroll
        for (int q = 0; q < 4; q++)
            split4(&Ah[arow][acb + q * 4], &Al[arow][acb + q * 4], pa[q]);
        *(uint4*)&Bh[brow][bcb]     = pbh0;
        *(uint4*)&Bh[brow][bcb + 8] = pbh1;
        *(uint4*)&Bl[brow][bcb]     = pbl0;
        *(uint4*)&Bl[brow][bcb + 8] = pbl1;
        __syncthreads();

        if (k0 + 32 < H_DIM) {   // prefetch next tile (overlaps mma below)
            #pragma unroll
            for (int q = 0; q < 4; q++)
                pa[q] = *(const float4*)&A[(size_t)(m0 + arow) * H_DIM + k0 + 32 + acb + q * 4];
            const size_t src = (size_t)(k0 + 32 + brow) * H3 + n0 + bcb;
            pbh0 = *(const uint4*)&g_wi_h[src];
            pbh1 = *(const uint4*)&g_wi_h[src + 8];
            pbl0 = *(const uint4*)&g_wi_l[src];
            pbl1 = *(const uint4*)&g_wi_l[src + 8];
        }

        #pragma unroll
        for (int ks = 0; ks < 2; ks++) {
            const int kk = ks * 16;
            uint32_t afh[2][4], afl[2][4];
            #pragma unroll
            for (int mb = 0; mb < 2; mb++) {
                const int r = wm + mb * 16 + (lane & 15);
                const int c = kk + (lane >> 4) * 8;
                ldsm_x4(afh[mb], smem_u32(&Ah[r][c]));
                ldsm_x4(afl[mb], smem_u32(&Al[r][c]));
            }
            #pragma unroll
            for (int nb = 0; nb < 8; nb++) {
                uint32_t bfh[2], bfl[2];
                const int br2 = kk + (lane & 15);
                const int bc2 = wn + nb * 8;
                ldsm_x2t(bfh, smem_u32(&Bh[br2][bc2]));
                ldsm_x2t(bfl, smem_u32(&Bl[br2][bc2]));
                #pragma unroll
                for (int mb = 0; mb < 2; mb++) {
                    mma_bf16(acc[mb][nb], afh[mb], bfh);
                    mma_bf16(acc[mb][nb], afh[mb], bfl);
                    mma_bf16(acc[mb][nb], afl[mb], bfh);
                }
            }
        }
        __syncthreads();
    }

    #pragma unroll
    for (int nb = 0; nb < 8; nb++) {
        const int col = n0 + wn + nb * 8 + 2 * tg;
        const float2 bb = *(const float2*)&bi[col];
        #pragma unroll
        for (int mb = 0; mb < 2; mb++) {
            const int row = m0 + wm + mb * 16 + g;
            float2 o0 = { acc[mb][nb][0] + bb.x, acc[mb][nb][1] + bb.y };
            float2 o1 = { acc[mb][nb][2] + bb.x, acc[mb][nb][3] + bb.y };
            *(float2*)&g_gi[(size_t)row * H3 + col]       = o0;
            *(float2*)&g_gi[(size_t)(row + 8) * H3 + col] = o1;
        }
    }
}

// ---------------------------------------------------------------------------
// Kernel 2: prep (wave schedule + barrier reset)
// ---------------------------------------------------------------------------
__global__ __launch_bounds__(256) void prep(const int* __restrict__ resets) {
    __shared__ int s_cnt[T_DIM];
    __shared__ int s_cur[T_DIM];
    const int tid = threadIdx.x;
    for (int i = tid; i < T_DIM; i += 256) s_cnt[i] = 0;
    if (tid == 0) { g_bar_count = 0; g_bar_sense = 0; }
    __syncthreads();

    const int b = tid;
    int d = 0;
    for (int t = 0; t < T_DIM; t++) {
        const int rst = resets[t * B_DIM + b];
        d = (t == 0 || rst) ? 0 : d + 1;
        const unsigned mask = __match_any_sync(0xffffffffu, d);
        const int leader = __ffs(mask) - 1;
        if ((tid & 31) == leader) atomicAdd(&s_cnt[d], __popc(mask));
    }
    __syncthreads();
    if (tid == 0) {
        int acc = 0;
        for (int i = 0; i < T_DIM; i++) {
            const int c = s_cnt[i];
            g_wave_cnt[i] = c;
            s_cur[i] = acc;
            acc += c;
        }
    }
    __syncthreads();
    d = 0;
    for (int t = 0; t < T_DIM; t++) {
        const int rst = resets[t * B_DIM + b];
        d = (t == 0 || rst) ? 0 : d + 1;
        const unsigned mask = __match_any_sync(0xffffffffu, d);
        const int leader = __ffs(mask) - 1;
        int base = 0;
        if ((tid & 31) == leader) base = atomicAdd(&s_cur[d], __popc(mask));
        base = __shfl_sync(0xffffffffu, base, leader);
        const int rank = __popc(mask & ((1u << (tid & 31)) - 1u));
        g_items[base + rank] = (t << 8) | b;
    }
}

// ---------------------------------------------------------------------------
// Grid barrier over gridDim.x CTAs
// ---------------------------------------------------------------------------
__device__ __forceinline__ void grid_barrier(unsigned& sense) {
    __syncthreads();
    sense ^= 1u;
    if (threadIdx.x == 0) {
        __threadfence();
        const unsigned pos = atomicAdd(&g_bar_count, 1u);
        if (pos == gridDim.x - 1) {
            atomicExch(&g_bar_count, 0u);
            __threadfence();
            g_bar_sense = sense;
        } else {
            while (g_bar_sense != sense) { __nanosleep(40); }
            __threadfence();
        }
    }
    __syncthreads();
}

// ---------------------------------------------------------------------------
// Kernel 3: wave GEMM scan — tensor cores, pipelined, 2 CTAs/SM (grid 296).
// Tile: 64 items x 64 j-cols x 3 gates. BK=32. 8 warps: 2(M) x 4(J).
// ---------------------------------------------------------------------------
#define LDBw 200
__global__ __launch_bounds__(256, 2) void gru_waves(
    const float* __restrict__ carry,    // [B,H]
    const int*   __restrict__ resets,   // [T,B]
    const float* __restrict__ bhn,      // [H]
    float*       __restrict__ out)      // [T,B,H]
{
    __shared__ __align__(16) __nv_bfloat16 Ah[64][LDA], Al[64][LDA];
    __shared__ __align__(16) __nv_bfloat16 Bh[32][LDBw], Bl[32][LDBw];
    __shared__ const float* s_ptr[64];
    __shared__ int s_item[64];

    const int tid = threadIdx.x;
    const int wid = tid >> 5, lane = tid & 31;
    const int wm = (wid >> 2) * 32, wj = (wid & 3) * 16;
    const int g = lane >> 2, tg = lane & 3;

    const int garow = tid >> 2, gacb = (tid & 3) * 8;   // A: 64 x 32
    const int gbrow = tid >> 3, gbcb = (tid & 7) * 8;   // B per gate: 32 x 64

    unsigned sense = 0;
    int off = 0;

    for (int w = 0; w < T_DIM; w++) {
        const int n = g_wave_cnt[w];
        if (n == 0) break;
        const int ntiles = ((n + 63) >> 6) << 2;

        for (int tile = blockIdx.x; tile < ntiles; tile += gridDim.x) {
            const int m0 = (tile >> 2) << 6;
            const int j0 = (tile & 3) << 6;

            __syncthreads();
            if (tid < 64) {
                const int m = m0 + tid;
                const float* p = nullptr;
                int item = 0;
                if (m < n) {
                    item = g_items[off + m];
                    const int t = item >> 8;
                    const int b = item & 255;
                    if (!resets[t * B_DIM + b])
                        p = (t == 0) ? (carry + (size_t)b * H_DIM)
                                     : (out + ((size_t)(t - 1) * B_DIM + b) * H_DIM);
                }
                s_ptr[tid]  = p;
                s_item[tid] = item;
            }
            __syncthreads();

            float acc[2][2][3][4];
            #pragma unroll
            for (int mb = 0; mb < 2; mb++)
                #pragma unroll
                for (int jb = 0; jb < 2; jb++)
                    #pragma unroll
                    for (int gg = 0; gg < 3; gg++)
                        #pragma unroll
                        for (int q = 0; q < 4; q++) acc[mb][jb][gg][q] = 0.f;

            const float* p = s_ptr[garow];

            // prefetch k0 = 0
            float4 va[2];
            uint4 vbh[3], vbl[3];
            #pragma unroll
            for (int q = 0; q < 2; q++)
                va[q] = p ? *(const float4*)(p + gacb + q * 4)
                          : make_float4(0.f, 0.f, 0.f, 0.f);
            #pragma unroll
            for (int gg = 0; gg < 3; gg++) {
                const size_t src = (size_t)gbrow * H3 + gg * H_DIM + j0 + gbcb;
                vbh[gg] = *(const uint4*)&g_wh_h[src];
                vbl[gg] = *(const uint4*)&g_wh_l[src];
            }

            for (int k0 = 0; k0 < H_DIM; k0 += 32) {
                #pragma unroll
                for (int q = 0; q < 2; q++)
                    split4(&Ah[garow][gacb + q * 4], &Al[garow][gacb + q * 4], va[q]);
                #pragma unroll
                for (int gg = 0; gg < 3; gg++) {
                    *(uint4*)&Bh[gbrow][gg * 64 + gbcb] = vbh[gg];
                    *(uint4*)&Bl[gbrow][gg * 64 + gbcb] = vbl[gg];
                }
                __syncthreads();

                if (k0 + 32 < H_DIM) {   // prefetch next (overlaps mma)
                    #pragma unroll
                    for (int q = 0; q < 2; q++)
                        va[q] = p ? *(const float4*)(p + k0 + 32 + gacb + q * 4)
                                  : make_float4(0.f, 0.f, 0.f, 0.f);
                    #pragma unroll
                    for (int gg = 0; gg < 3; gg++) {
                        const size_t src = (size_t)(k0 + 32 + gbrow) * H3 + gg * H_DIM + j0 + gbcb;
                        vbh[gg] = *(const uint4*)&g_wh_h[src];
                        vbl[gg] = *(const uint4*)&g_wh_l[src];
                    }
                }

                #pragma unroll
                for (int ks = 0; ks < 2; ks++) {
                    const int kk = ks * 16;
                    uint32_t afh[2][4], afl[2][4];
                    #pragma unroll
                    for (int mb = 0; mb < 2; mb++) {
                        const int r = wm + mb * 16 + (lane & 15);
                        const int c = kk + (lane >> 4) * 8;
                        ldsm_x4(afh[mb], smem_u32(&Ah[r][c]));
                        ldsm_x4(afl[mb], smem_u32(&Al[r][c]));
                    }
                    #pragma unroll
                    for (int gg = 0; gg < 3; gg++) {
                        #pragma unroll
                        for (int jb = 0; jb < 2; jb++) {
                            uint32_t bfh[2], bfl[2];
                            const int br2 = kk + (lane & 15);
                            const int bc2 = gg * 64 + wj + jb * 8;
                            ldsm_x2t(bfh, smem_u32(&Bh[br2][bc2]));
                            ldsm_x2t(bfl, smem_u32(&Bl[br2][bc2]));
                            #pragma unroll
                            for (int mb = 0; mb < 2; mb++) {
                                mma_bf16(acc[mb][jb][gg], afh[mb], bfh);
                                mma_bf16(acc[mb][jb][gg], afh[mb], bfl);
                                mma_bf16(acc[mb][jb][gg], afl[mb], bfh);
                            }
                        }
                    }
                }
                __syncthreads();
            }

            // Fused GRU epilogue
            #pragma unroll
            for (int jb = 0; jb < 2; jb++) {
                const int j = j0 + wj + jb * 8 + 2 * tg;
                const float2 bn2 = *(const float2*)&bhn[j];
                #pragma unroll
                for (int mb = 0; mb < 2; mb++) {
                    #pragma unroll
                    for (int half = 0; half < 2; half++) {
                        const int lm = wm + mb * 16 + g + half * 8;
                        if (m0 + lm >= n) continue;
                        const int item = s_item[lm];
                        const float* hp_ptr = s_ptr[lm];
                        const float* gip = g_gi + (size_t)item * H3 + j;
                        const float2 gr = *(const float2*)gip;
                        const float2 gz = *(const float2*)(gip + H_DIM);
                        const float2 gn = *(const float2*)(gip + 2 * H_DIM);
                        float2 hp = hp_ptr ? *(const float2*)(hp_ptr + j)
                                           : make_float2(0.f, 0.f);
                        const float aR0 = acc[mb][jb][0][half * 2 + 0];
                        const float aR1 = acc[mb][jb][0][half * 2 + 1];
                        const float aZ0 = acc[mb][jb][1][half * 2 + 0];
                        const float aZ1 = acc[mb][jb][1][half * 2 + 1];
                        const float aN0 = acc[mb][jb][2][half * 2 + 0];
                        const float aN1 = acc[mb][jb][2][half * 2 + 1];
                        const float r0 = 1.f / (1.f + expf(-(gr.x + aR0)));
                        const float r1 = 1.f / (1.f + expf(-(gr.y + aR1)));
                        const float z0 = 1.f / (1.f + expf(-(gz.x + aZ0)));
                        const float z1 = 1.f / (1.f + expf(-(gz.y + aZ1)));
                        const float n0 = tanhf(gn.x + r0 * (aN0 + bn2.x));
                        const float n1 = tanhf(gn.y + r1 * (aN1 + bn2.y));
                        float2 o;
                        o.x = (1.f - z0) * n0 + z0 * hp.x;
                        o.y = (1.f - z1) * n1 + z1 * hp.y;
                        *(float2*)(out + (size_t)item * H_DIM + j) = o;
                    }
                }
            }
        }

        off += n;
        grid_barrier(sense);
    }
}

// ---------------------------------------------------------------------------
extern "C" void kernel_launch(void* const* d_in, const int* in_sizes, int n_in,
                              void* d_out, int out_size) {
    const float* ins    = (const float*)d_in[0];   // [T,B,H]
    const int*   resets = (const int*)d_in[1];     // [T,B] int32 (bool promoted)
    const float* carry  = (const float*)d_in[2];   // [B,H]
    const float* Wi     = (const float*)d_in[3];   // [H,3H]
    const float* bi     = (const float*)d_in[4];   // [3H]
    const float* Wh     = (const float*)d_in[5];   // [H,3H]
    const float* bhn    = (const float*)d_in[6];   // [H]
    float*       out    = (float*)d_out;           // [T,B,H]

    // Phase 0: split weights to bf16 hi/lo
    w_prep<<<(H_DIM * H3 + 255) / 256, 256>>>(Wi, Wh);

    // Phase 1: all input gates via tensor cores
    dim3 g1(H3 / 128, M_TOT / 128);
    gi_gemm<<<g1, 256>>>(ins, bi);

    // Phase 2: wave schedule from resets (+ barrier state reset)
    prep<<<1, 256>>>(resets);

    // Phase 3: dependency waves — persistent, 2 CTAs/SM
    gru_waves<<<NCTA2, 256>>>(carry, resets, bhn, out);
}